// round 4
// baseline (speedup 1.0000x reference)
#include <cuda_runtime.h>

#define N_NODES 50000
#define N_EDGES 800000
#define D_IN    64
#define D_CAT   256   // SCALES * D_OUT = 4 * 64

// ---------------- scratch (static __device__: no allocations allowed) ----------
__device__ float    g_H[(size_t)N_NODES * D_CAT];   // 51.2 MB: H = x @ W_cat
__device__ float    g_dinv[N_NODES];                // degree, then deg^{-1/2}
__device__ unsigned g_mm[2];                        // [0]=min bits, [1]=max bits (weights >= 0)

// ---------------- 1) init ------------------------------------------------------
__global__ void k_init() {
    int i = blockIdx.x * blockDim.x + threadIdx.x;
    if (i < N_NODES) g_dinv[i] = 1.0f;     // self-loop weight 1 pre-added to degree
    if (i == 0) { g_mm[0] = 0x7F800000u; g_mm[1] = 0u; }
}

// ---------------- 2) min/max of edge weights (block-reduced, few global atomics)
__global__ void k_minmax(const float* __restrict__ ew) {
    unsigned lmin = 0x7F800000u, lmax = 0u;
    for (int i = blockIdx.x * blockDim.x + threadIdx.x; i < N_EDGES;
         i += gridDim.x * blockDim.x) {
        unsigned b = __float_as_uint(ew[i]);  // nonneg floats: uint order == float order
        lmin = min(lmin, b);
        lmax = max(lmax, b);
    }
    lmin = __reduce_min_sync(0xffffffffu, lmin);
    lmax = __reduce_max_sync(0xffffffffu, lmax);
    __shared__ unsigned smin[8], smax[8];
    int wid = threadIdx.x >> 5, lane = threadIdx.x & 31;
    if (lane == 0) { smin[wid] = lmin; smax[wid] = lmax; }
    __syncthreads();
    if (threadIdx.x == 0) {
        unsigned bmin = smin[0], bmax = smax[0];
        int nw = (blockDim.x + 31) >> 5;
        for (int w = 1; w < nw; w++) { bmin = min(bmin, smin[w]); bmax = max(bmax, smax[w]); }
        atomicMin(&g_mm[0], bmin);
        atomicMax(&g_mm[1], bmax);
    }
}

// ---------------- 3) weighted degree (scatter scalar) --------------------------
__global__ void k_degree(const int* __restrict__ ei, const float* __restrict__ ew) {
    float mn  = __uint_as_float(g_mm[0]);
    float inv = 1.0f / (__uint_as_float(g_mm[1]) - mn);
    int e = blockIdx.x * blockDim.x + threadIdx.x;
    if (e < N_EDGES) {
        float w = (ew[e] - mn) * inv;
        atomicAdd(&g_dinv[ei[N_EDGES + e]], w);   // col = edge_index[1][e]
    }
}

// ---------------- 4) deg -> deg^{-1/2} -----------------------------------------
__global__ void k_rsqrt() {
    int i = blockIdx.x * blockDim.x + threadIdx.x;
    if (i < N_NODES) g_dinv[i] = rsqrtf(g_dinv[i]);  // deg >= 1 always (self-loop)
}

// ---------------- 5) GEMM H = x @ W_cat  (+ fused self-loop/bias epilogue) -----
// Tile: 64 rows x 256 cols per block, K=64 in chunks of 16.
// Thread layout: tx = t&31 (8 cols each), ty = t>>5 (8 rows each) -> 8x8 acc.
__global__ void __launch_bounds__(256) k_gemm(const float* __restrict__ x,
                                              const float* __restrict__ Ws,
                                              const float* __restrict__ bs,
                                              float* __restrict__ out) {
    __shared__ float xs[64 * 16];    // 4 KB
    __shared__ float ws[16 * 256];   // 16 KB
    const int tx = threadIdx.x & 31;
    const int ty = threadIdx.x >> 5;
    const int row0 = blockIdx.x * 64;

    float acc[8][8];
#pragma unroll
    for (int i = 0; i < 8; i++)
#pragma unroll
        for (int j = 0; j < 8; j++) acc[i][j] = 0.0f;

    for (int kt = 0; kt < 4; kt++) {
        // x tile: 64 rows x 16 k
#pragma unroll
        for (int s = 0; s < 4; s++) {
            int idx = threadIdx.x + 256 * s;
            int r = idx >> 4, kk = idx & 15;
            int gr = row0 + r;
            xs[idx] = (gr < N_NODES) ? x[(size_t)gr * D_IN + kt * 16 + kk] : 0.0f;
        }
        // W_cat tile: 16 k x 256 cols; col c=(i*64+j) lives at Ws[((c>>6)*64 + k)*64 + (c&63)]
#pragma unroll
        for (int s = 0; s < 16; s++) {
            int idx = threadIdx.x + 256 * s;
            int kk = idx >> 8, c = idx & 255;
            int k = kt * 16 + kk;
            ws[idx] = Ws[(size_t)((c >> 6) * 64 + k) * 64 + (c & 63)];
        }
        __syncthreads();
#pragma unroll
        for (int k = 0; k < 16; k++) {
            float xa[8];
#pragma unroll
            for (int i = 0; i < 8; i++) xa[i] = xs[(ty * 8 + i) * 16 + k];  // warp broadcast
            float4 w0 = *(const float4*)&ws[k * 256 + tx * 8];
            float4 w1 = *(const float4*)&ws[k * 256 + tx * 8 + 4];
            float wb[8] = {w0.x, w0.y, w0.z, w0.w, w1.x, w1.y, w1.z, w1.w};
#pragma unroll
            for (int i = 0; i < 8; i++)
#pragma unroll
                for (int j = 0; j < 8; j++) acc[i][j] += xa[i] * wb[j];
        }
        __syncthreads();
    }

    // epilogue: write H, and out = bias + H * dinv^2 (self-loop term; edges add later)
#pragma unroll
    for (int i = 0; i < 8; i++) {
        int r = row0 + ty * 8 + i;
        if (r >= N_NODES) break;
        float di = g_dinv[r];
        float dd = di * di;
#pragma unroll
        for (int j = 0; j < 8; j += 4) {
            int c = tx * 8 + j;
            float4 h = make_float4(acc[i][j], acc[i][j + 1], acc[i][j + 2], acc[i][j + 3]);
            *(float4*)&g_H[(size_t)r * D_CAT + c] = h;
            float4 b = *(const float4*)&bs[c];
            float4 o = make_float4(b.x + h.x * dd, b.y + h.y * dd,
                                   b.z + h.z * dd, b.w + h.w * dd);
            *(float4*)&out[(size_t)r * D_CAT + c] = o;
        }
    }
}

// ---------------- 6) edge scatter: one warp per edge, scalar RED.ADD.F32 -------
__global__ void __launch_bounds__(256) k_edges(const int* __restrict__ ei,
                                               const float* __restrict__ ew,
                                               float* __restrict__ out) {
    int gw = (blockIdx.x * blockDim.x + threadIdx.x) >> 5;  // one warp per edge
    int lane = threadIdx.x & 31;
    if (gw >= N_EDGES) return;

    int r = ei[gw];               // row = edge_index[0][e]
    int c = ei[N_EDGES + gw];     // col = edge_index[1][e]
    float mn  = __uint_as_float(g_mm[0]);
    float inv = 1.0f / (__uint_as_float(g_mm[1]) - mn);
    float w   = (ew[gw] - mn) * inv;
    float nrm = g_dinv[r] * w * g_dinv[c];

    const float4* hp = (const float4*)(g_H + (size_t)r * D_CAT);
    float*        op = out + (size_t)c * D_CAT;

    float4 h0 = hp[lane];        // 256 floats = 64 float4: lanes cover [0,32) and [32,64)
    float4 h1 = hp[lane + 32];
    // scalar reductions (result unused -> RED.E.ADD.F32); addresses consecutive
    // across the warp, so they pack into full 32B L2 sectors.
    atomicAdd(op + lane * 4 + 0, h0.x * nrm);
    atomicAdd(op + lane * 4 + 1, h0.y * nrm);
    atomicAdd(op + lane * 4 + 2, h0.z * nrm);
    atomicAdd(op + lane * 4 + 3, h0.w * nrm);
    atomicAdd(op + (lane + 32) * 4 + 0, h1.x * nrm);
    atomicAdd(op + (lane + 32) * 4 + 1, h1.y * nrm);
    atomicAdd(op + (lane + 32) * 4 + 2, h1.z * nrm);
    atomicAdd(op + (lane + 32) * 4 + 3, h1.w * nrm);
}

// ---------------- launch -------------------------------------------------------
extern "C" void kernel_launch(void* const* d_in, const int* in_sizes, int n_in,
                              void* d_out, int out_size) {
    // Resolve inputs by element count (all five are distinct) — immune to
    // metadata ordering:
    //   x          : 50000*64   = 3,200,000 f32
    //   edge_index : 2*800000   = 1,600,000 i32  (JAX x64 disabled -> int32!)
    //   edge_weight: 800,000 f32
    //   Ws         : 4*64*64    = 16,384 f32
    //   bs         : 4*64       = 256 f32
    const float* x  = nullptr;
    const int*   ei = nullptr;
    const float* ew = nullptr;
    const float* Ws = nullptr;
    const float* bs = nullptr;
    for (int i = 0; i < n_in; i++) {
        switch (in_sizes[i]) {
            case 3200000: x  = (const float*)d_in[i]; break;
            case 1600000: ei = (const int*)d_in[i];   break;
            case  800000: ew = (const float*)d_in[i]; break;
            case   16384: Ws = (const float*)d_in[i]; break;
            case     256: bs = (const float*)d_in[i]; break;
        }
    }
    float* out = (float*)d_out;  // [50000, 256]

    k_init<<<(N_NODES + 255) / 256, 256>>>();
    k_minmax<<<148, 256>>>(ew);
    k_degree<<<(N_EDGES + 255) / 256, 256>>>(ei, ew);
    k_rsqrt<<<(N_NODES + 255) / 256, 256>>>();
    k_gemm<<<(N_NODES + 63) / 64, 256>>>(x, Ws, bs, out);
    k_edges<<<(N_EDGES * 32 + 255) / 256, 256>>>(ei, ew, out);
}

// round 5
// speedup vs baseline: 4.0327x; 4.0327x over previous
#include <cuda_runtime.h>

#define N_NODES 50000
#define N_EDGES 800000
#define D_IN    64
#define D_CAT   256   // SCALES * D_OUT = 4 * 64

// ---------------- scratch (static __device__: no allocations allowed) ----------
__device__ float    g_A[(size_t)N_NODES * D_IN];    // 12.8 MB: aggregated x (pre-GEMM)
__device__ float    g_dinv[N_NODES];                // degree, then deg^{-1/2}
__device__ unsigned g_mm[2];                        // [0]=min bits, [1]=max bits (weights >= 0)

// ---------------- 1) init ------------------------------------------------------
__global__ void k_init() {
    int i = blockIdx.x * blockDim.x + threadIdx.x;
    if (i < N_NODES) g_dinv[i] = 1.0f;     // self-loop weight 1 pre-added to degree
    if (i == 0) { g_mm[0] = 0x7F800000u; g_mm[1] = 0u; }
}

// ---------------- 2) min/max of edge weights (block-reduced, few global atomics)
__global__ void k_minmax(const float* __restrict__ ew) {
    unsigned lmin = 0x7F800000u, lmax = 0u;
    for (int i = blockIdx.x * blockDim.x + threadIdx.x; i < N_EDGES;
         i += gridDim.x * blockDim.x) {
        unsigned b = __float_as_uint(ew[i]);  // nonneg floats: uint order == float order
        lmin = min(lmin, b);
        lmax = max(lmax, b);
    }
    lmin = __reduce_min_sync(0xffffffffu, lmin);
    lmax = __reduce_max_sync(0xffffffffu, lmax);
    __shared__ unsigned smin[8], smax[8];
    int wid = threadIdx.x >> 5, lane = threadIdx.x & 31;
    if (lane == 0) { smin[wid] = lmin; smax[wid] = lmax; }
    __syncthreads();
    if (threadIdx.x == 0) {
        unsigned bmin = smin[0], bmax = smax[0];
        int nw = (blockDim.x + 31) >> 5;
        for (int w = 1; w < nw; w++) { bmin = min(bmin, smin[w]); bmax = max(bmax, smax[w]); }
        atomicMin(&g_mm[0], bmin);
        atomicMax(&g_mm[1], bmax);
    }
}

// ---------------- 3) weighted degree (scatter scalar) --------------------------
__global__ void k_degree(const int* __restrict__ ei, const float* __restrict__ ew) {
    float mn  = __uint_as_float(g_mm[0]);
    float inv = 1.0f / (__uint_as_float(g_mm[1]) - mn);
    int e = blockIdx.x * blockDim.x + threadIdx.x;
    if (e < N_EDGES) {
        float w = (ew[e] - mn) * inv;
        atomicAdd(&g_dinv[ei[N_EDGES + e]], w);   // col = edge_index[1][e]
    }
}

// ---------------- 4) deg -> deg^{-1/2} -----------------------------------------
__global__ void k_rsqrt() {
    int i = blockIdx.x * blockDim.x + threadIdx.x;
    if (i < N_NODES) g_dinv[i] = rsqrtf(g_dinv[i]);  // deg >= 1 always (self-loop)
}

// ---------------- 5) A := dinv^2 * x  (self-loop term, vectorized) -------------
__global__ void k_selfinit(const float* __restrict__ x) {
    int idx = blockIdx.x * blockDim.x + threadIdx.x;     // over 800000 float4s
    if (idx >= N_NODES * (D_IN / 4)) return;
    int row = idx >> 4;                                  // 16 float4 per row
    float di = g_dinv[row];
    float dd = di * di;
    float4 v = ((const float4*)x)[idx];
    v.x *= dd; v.y *= dd; v.z *= dd; v.w *= dd;
    ((float4*)g_A)[idx] = v;
}

// ---------------- 6) edge scatter into x-space: A[col] += norm * x[row] --------
// One warp owns 32 edges: coalesced index/weight loads, then per-edge shfl
// broadcast; lanes cover the 64 columns with float2 gather + 2 scalar REDs.
__global__ void __launch_bounds__(256) k_edges(const int* __restrict__ ei,
                                               const float* __restrict__ ew,
                                               const float* __restrict__ x) {
    int lane  = threadIdx.x & 31;
    int gwarp = (blockIdx.x * blockDim.x + threadIdx.x) >> 5;
    int e0 = gwarp * 32;                 // N_EDGES = 800000 = 25000 * 32: no tail
    int e  = e0 + lane;

    float mn  = __uint_as_float(g_mm[0]);
    float inv = 1.0f / (__uint_as_float(g_mm[1]) - mn);

    int   r = ei[e];
    int   c = ei[N_EDGES + e];
    float w = (ew[e] - mn) * inv;
    float nrm = g_dinv[r] * w * g_dinv[c];

#pragma unroll 4
    for (int i = 0; i < 32; i++) {
        int   rr = __shfl_sync(0xffffffffu, r, i);
        int   cc = __shfl_sync(0xffffffffu, c, i);
        float nn = __shfl_sync(0xffffffffu, nrm, i);
        float2 v = *(const float2*)(x + (size_t)rr * D_IN + lane * 2);
        float* dst = g_A + (size_t)cc * D_IN + lane * 2;
        atomicAdd(dst + 0, v.x * nn);
        atomicAdd(dst + 1, v.y * nn);
    }
}

// ---------------- 7) GEMM out = A @ W_cat + b ----------------------------------
// Tile: 64 rows x 256 cols per block, K=64 in chunks of 16.
// Thread layout: tx = t&31 (8 cols each), ty = t>>5 (8 rows each) -> 8x8 acc.
__global__ void __launch_bounds__(256) k_gemm(const float* __restrict__ Ws,
                                              const float* __restrict__ bs,
                                              float* __restrict__ out) {
    __shared__ float xs[64 * 16];    // 4 KB
    __shared__ float ws[16 * 256];   // 16 KB
    const int tx = threadIdx.x & 31;
    const int ty = threadIdx.x >> 5;
    const int row0 = blockIdx.x * 64;

    float acc[8][8];
#pragma unroll
    for (int i = 0; i < 8; i++)
#pragma unroll
        for (int j = 0; j < 8; j++) acc[i][j] = 0.0f;

    for (int kt = 0; kt < 4; kt++) {
        // A tile: 64 rows x 16 k
#pragma unroll
        for (int s = 0; s < 4; s++) {
            int idx = threadIdx.x + 256 * s;
            int r = idx >> 4, kk = idx & 15;
            int gr = row0 + r;
            xs[idx] = (gr < N_NODES) ? g_A[(size_t)gr * D_IN + kt * 16 + kk] : 0.0f;
        }
        // W_cat tile: 16 k x 256 cols; col c=(s*64+j) lives at Ws[((c>>6)*64 + k)*64 + (c&63)]
#pragma unroll
        for (int s = 0; s < 16; s++) {
            int idx = threadIdx.x + 256 * s;
            int kk = idx >> 8, c = idx & 255;
            int k = kt * 16 + kk;
            ws[idx] = Ws[(size_t)((c >> 6) * 64 + k) * 64 + (c & 63)];
        }
        __syncthreads();
#pragma unroll
        for (int k = 0; k < 16; k++) {
            float xa[8];
#pragma unroll
            for (int i = 0; i < 8; i++) xa[i] = xs[(ty * 8 + i) * 16 + k];  // warp broadcast
            float4 w0 = *(const float4*)&ws[k * 256 + tx * 8];
            float4 w1 = *(const float4*)&ws[k * 256 + tx * 8 + 4];
            float wb[8] = {w0.x, w0.y, w0.z, w0.w, w1.x, w1.y, w1.z, w1.w};
#pragma unroll
            for (int i = 0; i < 8; i++)
#pragma unroll
                for (int j = 0; j < 8; j++) acc[i][j] += xa[i] * wb[j];
        }
        __syncthreads();
    }

    // epilogue: out = acc + bias
#pragma unroll
    for (int i = 0; i < 8; i++) {
        int r = row0 + ty * 8 + i;
        if (r >= N_NODES) break;
#pragma unroll
        for (int j = 0; j < 8; j += 4) {
            int c = tx * 8 + j;
            float4 b = *(const float4*)&bs[c];
            float4 o = make_float4(acc[i][j] + b.x, acc[i][j + 1] + b.y,
                                   acc[i][j + 2] + b.z, acc[i][j + 3] + b.w);
            *(float4*)&out[(size_t)r * D_CAT + c] = o;
        }
    }
}

// ---------------- launch -------------------------------------------------------
extern "C" void kernel_launch(void* const* d_in, const int* in_sizes, int n_in,
                              void* d_out, int out_size) {
    // Resolve inputs by element count (all five are distinct):
    //   x=3,200,000 f32 | edge_index=1,600,000 i32 | edge_weight=800,000 f32
    //   Ws=16,384 f32   | bs=256 f32
    const float* x  = nullptr;
    const int*   ei = nullptr;
    const float* ew = nullptr;
    const float* Ws = nullptr;
    const float* bs = nullptr;
    for (int i = 0; i < n_in; i++) {
        switch (in_sizes[i]) {
            case 3200000: x  = (const float*)d_in[i]; break;
            case 1600000: ei = (const int*)d_in[i];   break;
            case  800000: ew = (const float*)d_in[i]; break;
            case   16384: Ws = (const float*)d_in[i]; break;
            case     256: bs = (const float*)d_in[i]; break;
        }
    }
    float* out = (float*)d_out;  // [50000, 256]

    k_init<<<(N_NODES + 255) / 256, 256>>>();
    k_minmax<<<148, 256>>>(ew);
    k_degree<<<(N_EDGES + 255) / 256, 256>>>(ei, ew);
    k_rsqrt<<<(N_NODES + 255) / 256, 256>>>();
    k_selfinit<<<(N_NODES * (D_IN / 4) + 255) / 256, 256>>>(x);
    k_edges<<<(N_EDGES / 32) * 32 / 256, 256>>>(ei, ew, x);   // 3125 blocks
    k_gemm<<<(N_NODES + 63) / 64, 256>>>(Ws, bs, out);
}